// round 9
// baseline (speedup 1.0000x reference)
#include <cuda_runtime.h>
#include <cuda_fp16.h>
#include <math_constants.h>
#include <cstdint>

#define TOKENS  32768
#define DIM     2048
#define NE      64
#define TOPK    6
#define MT      64                  // tokens per CTA
#define KCH     32                  // K per chunk
#define NCH     (DIM / KCH)         // 64
#define NTH     128
#define WSCALE_INV 0.03125f         // w pre-scaled by 32 in split kernel

// smem map (dynamic): x 3x8KB | w 3x8KB | bias
#define OFFX    0
#define XBUF    8192
#define OFFW    24576
#define WBUF    8192
#define OFFB    49152
#define SMEMSZ  49408

// pre-split (fp16, w*32), pre-swizzled weights: [term][chunk][64 experts x 64B]
__device__ __align__(16) unsigned char g_wsw[2][NCH][NE * KCH * 2];

__device__ __forceinline__ unsigned su32(const void* p) {
    return (unsigned)__cvta_generic_to_shared(p);
}
__device__ __forceinline__ void cp16(unsigned d, const void* s) {
    asm volatile("cp.async.cg.shared.global [%0], [%1], 16;" :: "r"(d), "l"(s));
}
// 2-term fp16 split of (f0,f1): p1 = rn(f), p2 = rn(f - p1)
__device__ __forceinline__ void split2h(float f0, float f1, unsigned& p1, unsigned& p2) {
    __half2 h1 = __floats2half2_rn(f0, f1);
    p1 = *(unsigned*)&h1;
    float2 g = __half22float2(h1);
    __half2 h2 = __floats2half2_rn(f0 - g.x, f1 - g.y);
    p2 = *(unsigned*)&h2;
}
__device__ __forceinline__ void ldsm4(unsigned b[4], unsigned addr) {
    asm volatile("ldmatrix.sync.aligned.m8n8.x4.shared.b16 {%0,%1,%2,%3}, [%4];"
                 : "=r"(b[0]), "=r"(b[1]), "=r"(b[2]), "=r"(b[3]) : "r"(addr));
}
// accumulate: C += A*B (fp16 in, fp32 acc)
__device__ __forceinline__ void mma16816(float* c, const unsigned* a,
                                         unsigned b0, unsigned b1) {
    asm volatile(
        "mma.sync.aligned.m16n8k16.row.col.f32.f16.f16.f32 "
        "{%0,%1,%2,%3}, {%4,%5,%6,%7}, {%8,%9}, {%0,%1,%2,%3};"
        : "+f"(c[0]), "+f"(c[1]), "+f"(c[2]), "+f"(c[3])
        : "r"(a[0]), "r"(a[1]), "r"(a[2]), "r"(a[3]), "r"(b0), "r"(b1));
}
// zero-start: C = A*B
__device__ __forceinline__ void mma16816_z(float* c, const unsigned* a,
                                           unsigned b0, unsigned b1) {
    asm volatile(
        "mma.sync.aligned.m16n8k16.row.col.f32.f16.f16.f32 "
        "{%0,%1,%2,%3}, {%4,%5,%6,%7}, {%8,%9}, {%10,%11,%12,%13};"
        : "=f"(c[0]), "=f"(c[1]), "=f"(c[2]), "=f"(c[3])
        : "r"(a[0]), "r"(a[1]), "r"(a[2]), "r"(a[3]), "r"(b0), "r"(b1),
          "f"(0.0f), "f"(0.0f), "f"(0.0f), "f"(0.0f));
}

// ---- pre-kernel: 2-term fp16 split of 32*w, ldmatrix-swizzled rows of 64B ----
__global__ void split_w_kernel(const float* __restrict__ w) {
    int idx = blockIdx.x * 256 + threadIdx.x;     // e*DIM + k, < 131072
    int e = idx >> 11, k = idx & (DIM - 1);
    float v = w[idx] * 32.0f;                     // exact scale, undone in epilogue
    __half h1 = __float2half_rn(v);
    float f1 = __half2float(h1);
    __half h2 = __float2half_rn(v - f1);
    int c = k >> 5, kk = k & (KCH - 1);
    unsigned off = ((unsigned)e << 6) | ((unsigned)kk << 1);
    unsigned sw = off ^ (((off >> 7) & 3u) << 4);   // bits[5:4] ^= bits[8:7]
    *(unsigned short*)&g_wsw[0][c][sw] = *(unsigned short*)&h1;
    *(unsigned short*)&g_wsw[1][c][sw] = *(unsigned short*)&h2;
}

__global__ __launch_bounds__(NTH, 4)
void gate_hmma_kernel(const float* __restrict__ x,
                      const float* __restrict__ bias,
                      float* __restrict__ out) {
    extern __shared__ unsigned char sm[];

    const int tid = threadIdx.x;
    const int wid = tid >> 5;
    const int L   = tid & 31;
    const int r4  = L >> 2;          // 0..7
    const int cq  = L & 3;           // 0..3
    const int t0  = blockIdx.x * MT;

    if (tid < NE) ((float*)(sm + OFFB))[tid] = bias[tid];

    // ---- cp.async source/dest setup (slot-0 bases) ----
    const float* xsrc[4]; unsigned xdst[4];
#pragma unroll
    for (int i = 0; i < 4; i++) {
        int u = tid + NTH * i;               // 0..511 = 64 tokens x 8 16B units
        int tt = u >> 3, q = u & 7;
        xsrc[i] = x + (size_t)(t0 + tt) * DIM + q * 4;
        unsigned off = ((unsigned)tt << 7) | ((unsigned)q << 4);
        xdst[i] = su32(sm + OFFX) + (off ^ ((off >> 3) & 0x70u));
    }
    const unsigned char* wsrc[4]; unsigned wdst[4];
#pragma unroll
    for (int i = 0; i < 4; i++) {
        int u = tid + NTH * i;               // 0..511 = 2 terms x 256 units
        int trm = u >> 8; unsigned o = (unsigned)(u & 255) << 4;
        wsrc[i] = &g_wsw[trm][0][o];
        wdst[i] = su32(sm + OFFW) + trm * 4096 + o;
    }

    // fp32 running logits (IEEE adds), drained every 2 chunks
    float run[8][4];
#pragma unroll
    for (int n = 0; n < 8; n++)
#pragma unroll
        for (int i = 0; i < 4; i++) run[n][i] = 0.0f;

    // prologue: chunks 0 and 1 -> slots 0 and 1
#pragma unroll
    for (int sl = 0; sl < 2; sl++) {
#pragma unroll
        for (int i = 0; i < 4; i++) { cp16(xdst[i] + sl * XBUF, xsrc[i]); xsrc[i] += KCH; }
#pragma unroll
        for (int i = 0; i < 4; i++) { cp16(wdst[i] + sl * WBUF, wsrc[i]); wsrc[i] += 4096; }
        asm volatile("cp.async.commit_group;");
    }

    const int R0 = wid * 16 + r4;           // thread's token rows R0, R0+8
    int slot = 0, pf = 2;

    float cc[8][4];                          // 2-chunk-local tensor-core chains

    for (int ch = 0; ch < NCH; ch++) {
        if (ch < NCH - 1) {
            asm volatile("cp.async.wait_group 1;");
        } else {
            asm volatile("cp.async.wait_group 0;");
        }
        __syncthreads();   // chunk ch visible; all warps done reading slot pf

        // prefetch chunk ch+2 into slot pf (read at chunk ch-1)
        if (ch + 2 < NCH) {
#pragma unroll
            for (int i = 0; i < 4; i++) { cp16(xdst[i] + pf * XBUF, xsrc[i]); xsrc[i] += KCH; }
#pragma unroll
            for (int i = 0; i < 4; i++) { cp16(wdst[i] + pf * WBUF, wsrc[i]); wsrc[i] += 4096; }
            asm volatile("cp.async.commit_group;");
        }

        const unsigned xb = su32(sm + OFFX) + slot * XBUF;
        const unsigned wb = su32(sm + OFFW) + slot * WBUF;
        const bool zstart = (ch & 1) == 0;

#pragma unroll
        for (int s = 0; s < 2; s++) {       // two k16 steps per chunk
            // ---- A fragments: LDS pairs + 2-term fp16 split ----
            unsigned a1[4], a2[4];
#pragma unroll
            for (int half = 0; half < 2; half++) {
#pragma unroll
                for (int rowi = 0; rowi < 2; rowi++) {
                    int row = R0 + rowi * 8;
                    unsigned off = ((unsigned)row << 7)
                                 + ((unsigned)(s * 16 + cq * 2 + half * 8) << 2);
                    unsigned sw = off ^ ((off >> 3) & 0x70u);
                    float f0, f1;
                    asm volatile("ld.shared.v2.f32 {%0,%1}, [%2];"
                                 : "=f"(f0), "=f"(f1) : "r"(xb + sw));
                    int pi = half * 2 + rowi;   // a0,a1,a2,a3 order
                    split2h(f0, f1, a1[pi], a2[pi]);
                }
            }
            // ---- B terms + HMMA: 3 products per C per k-step ----
            const int m  = L >> 3;          // ldmatrix matrix id
            const int rr = L & 7;
#pragma unroll
            for (int p = 0; p < 4; p++) {
                int e = p * 16 + (m >> 1) * 8 + rr;
                unsigned off = ((unsigned)e << 6) + s * 32 + (m & 1) * 16;
                unsigned sw = off ^ (((off >> 7) & 3u) << 4);
                unsigned b1[4], b2[4];
                ldsm4(b1, wb + sw);             // w term 1
                ldsm4(b2, wb + 4096 + sw);      // w term 2
                if (zstart && s == 0) {
                    mma16816_z(cc[2 * p + 0], a1, b1[0], b1[1]);
                    mma16816_z(cc[2 * p + 1], a1, b1[2], b1[3]);
                } else {
                    mma16816(cc[2 * p + 0], a1, b1[0], b1[1]);
                    mma16816(cc[2 * p + 1], a1, b1[2], b1[3]);
                }
                mma16816(cc[2 * p + 0], a2, b1[0], b1[1]);
                mma16816(cc[2 * p + 1], a2, b1[2], b1[3]);
                mma16816(cc[2 * p + 0], a1, b2[0], b2[1]);
                mma16816(cc[2 * p + 1], a1, b2[2], b2[3]);
            }
        }
        // ---- drain every 2 chunks: IEEE fp32 adds ----
        if (ch & 1) {
#pragma unroll
            for (int nt = 0; nt < 8; nt++)
#pragma unroll
                for (int i = 0; i < 4; i++) run[nt][i] += cc[nt][i];
        }

        slot = (slot == 2) ? 0 : slot + 1;
        pf   = (pf   == 2) ? 0 : pf   + 1;
    }

    __syncthreads();   // all warps done with mainloop buffers before overlay

    // ---- scatter logits to smem [64][65] (overlays mainloop buffers) ----
    float* lg = (float*)sm;
#pragma unroll
    for (int nt = 0; nt < 8; nt++)
#pragma unroll
        for (int i = 0; i < 4; i++) {
            int tk = R0 + ((i >= 2) ? 8 : 0);         // c0,c1 row; c2,c3 row+8
            int ex = nt * 8 + cq * 2 + (i & 1);
            lg[tk * 65 + ex] = run[nt][i];
        }
    __syncthreads();

    if (tid < MT) {
        float sc[NE];
#pragma unroll
        for (int e = 0; e < NE; e++) sc[e] = lg[tid * 65 + e] * WSCALE_INV;  // undo w*32

        float mx = -CUDART_INF_F;
#pragma unroll
        for (int e = 0; e < NE; e++) mx = fmaxf(mx, sc[e]);
        float sum = 0.0f;
#pragma unroll
        for (int e = 0; e < NE; e++) { sc[e] = __expf(sc[e] - mx); sum += sc[e]; }
        float inv = 1.0f / sum;
#pragma unroll
        for (int e = 0; e < NE; e++) sc[e] *= inv;

        const float* bs = (const float*)(sm + OFFB);
        unsigned long long taken = 0ull;
        const int t = t0 + tid;
        float* wout = out + (size_t)t * TOPK;
        float* iout = out + (size_t)TOKENS * TOPK + (size_t)t * TOPK;

#pragma unroll
        for (int sidx = 0; sidx < TOPK; sidx++) {
            float best = -CUDART_INF_F;
            float bsc = 0.0f;
            int be = 0;
#pragma unroll
            for (int e = 0; e < NE; e++) {
                float v = sc[e] + bs[e];
                bool ok = ((taken >> e) & 1ull) == 0ull;
                if (ok && v > best) { best = v; bsc = sc[e]; be = e; }
            }
            taken |= (1ull << be);
            wout[sidx] = bsc;        // ROUTE_SCALE == 1.0
            iout[sidx] = (float)be;
        }
    }
}

extern "C" void kernel_launch(void* const* d_in, const int* in_sizes, int n_in,
                              void* d_out, int out_size) {
    const float* x    = (const float*)d_in[0];
    const float* w    = (const float*)d_in[1];
    const float* bias = (const float*)d_in[2];
    float* out        = (float*)d_out;

    cudaFuncSetAttribute(gate_hmma_kernel,
                         cudaFuncAttributeMaxDynamicSharedMemorySize, SMEMSZ);

    split_w_kernel<<<(NE * DIM) / 256, 256>>>(w);
    gate_hmma_kernel<<<TOKENS / MT, NTH, SMEMSZ>>>(x, bias, out);
}